// round 11
// baseline (speedup 1.0000x reference)
#include <cuda_runtime.h>
#include <math.h>
#include <stdint.h>

#define BB 128
#define LL 100
#define HID 256
#define NCAP 1600
#define NCLS 19
#define ODIM 304

// ---------------- device scratch ----------------
__device__ float g_xgf [BB*LL*1024];
__device__ float g_xgb [BB*LL*1024];
__device__ float g_hbuf[4*2*BB*HID];          // quad-buffered h state
__device__ float g_xf  [BB*LL*HID];
__device__ float g_xb  [BB*LL*HID];
__device__ float g_att [BB*LL];
__device__ float g_u   [BB*NCAP*16];
__device__ float g_bb  [(size_t)BB*NCAP*NCLS];
__device__ float g_s   [BB*ODIM];
__device__ float g_v   [BB*ODIM];
__device__ __align__(64) int g_hflags[16][16]; // [dir*8+bt][ut]

// ---------------- packed fp32x2 helpers ----------------
__device__ __forceinline__ float2 ffma2(float2 a, float2 b, float2 c) {
    float2 d;
    asm("fma.rn.f32x2 %0, %1, %2, %3;"
        : "=l"(reinterpret_cast<unsigned long long&>(d))
        : "l"(reinterpret_cast<unsigned long long&>(a)),
          "l"(reinterpret_cast<unsigned long long&>(b)),
          "l"(reinterpret_cast<unsigned long long&>(c)));
    return d;
}
__device__ __forceinline__ float2 dup2(float x) {
    float2 d;
    asm("mov.b64 %0, {%1, %1};"
        : "=l"(reinterpret_cast<unsigned long long&>(d)) : "f"(x));
    return d;
}

// ---------------- K1: xg GEMM, f32x2, fused embed gather + state reset ----------------
// C[12800,1024] per dir, K=160. Block tile 64m x 128n, thread tile 4m x 8n.
#define GA_S 68
#define GW_S 136
__global__ void __launch_bounds__(256) gemm_xg_kernel(
        const int* __restrict__ word, const int* __restrict__ tag,
        const int* __restrict__ p1,   const int* __restrict__ p2,
        const float* __restrict__ we, const float* __restrict__ te,
        const float* __restrict__ p1e,const float* __restrict__ p2e,
        const float* __restrict__ wf, const float* __restrict__ wbk,
        const float* __restrict__ bif, const float* __restrict__ bhf,
        const float* __restrict__ bib, const float* __restrict__ bhb) {
    __shared__ float As[16*GA_S];    // [kk][m]
    __shared__ float Ws[16*GW_S];    // [kk][n]
    int dir = blockIdx.z;
    const float* W  = dir ? wbk : wf;
    const float* bi = dir ? bib : bif;
    const float* bh = dir ? bhb : bhf;
    float* C = dir ? g_xgb : g_xgf;
    int n0 = blockIdx.x * 128;
    int m0 = blockIdx.y * 64;
    int tid = threadIdx.x;
    int tx = tid & 15, ty = tid >> 4;
    int lrow = tid & 63,  lq = tid >> 6;    // A loader: 64 rows x 4 k-chunks
    int wrow = tid & 127, wq = tid >> 7;    // W loader: 128 rows x 2 k-chunks
    int bl = m0 + lrow;
    int wi = word[bl], ti = tag[bl], pi1 = p1[bl], pi2 = p2[bl];

    // fold per-replay reset of lstm h-slot0 + flags into this kernel
    if (dir == 0 && blockIdx.x == 0 && blockIdx.y < 64) {
        ((float4*)g_hbuf)[blockIdx.y*256 + tid] = make_float4(0.f,0.f,0.f,0.f);
        if (blockIdx.y == 0 && tid < 64)
            ((int4*)g_hflags)[tid] = make_int4(0,0,0,0);
    }

    float2 acc[4][4];
    #pragma unroll
    for (int i = 0; i < 4; ++i)
        #pragma unroll
        for (int j = 0; j < 4; ++j) acc[i][j] = make_float2(0.f, 0.f);

    // stage-0 loads
    int d0 = lq*4;
    const float* asrc;
    if (d0 < 100)      asrc = we + (size_t)wi*100 + d0;
    else if (d0 < 120) asrc = te + ti*20 + (d0-100);
    else if (d0 < 140) asrc = p1e + pi1*20 + (d0-120);
    else               asrc = p2e + pi2*20 + (d0-140);
    float4 aR = *(const float4*)asrc;
    const float* wb0 = W + (size_t)(n0 + wrow)*160 + wq*8;
    float4 wR0 = *(const float4*)(wb0);
    float4 wR1 = *(const float4*)(wb0 + 4);
    As[(lq*4+0)*GA_S + lrow] = aR.x;
    As[(lq*4+1)*GA_S + lrow] = aR.y;
    As[(lq*4+2)*GA_S + lrow] = aR.z;
    As[(lq*4+3)*GA_S + lrow] = aR.w;
    Ws[(wq*8+0)*GW_S + wrow] = wR0.x;
    Ws[(wq*8+1)*GW_S + wrow] = wR0.y;
    Ws[(wq*8+2)*GW_S + wrow] = wR0.z;
    Ws[(wq*8+3)*GW_S + wrow] = wR0.w;
    Ws[(wq*8+4)*GW_S + wrow] = wR1.x;
    Ws[(wq*8+5)*GW_S + wrow] = wR1.y;
    Ws[(wq*8+6)*GW_S + wrow] = wR1.z;
    Ws[(wq*8+7)*GW_S + wrow] = wR1.w;
    __syncthreads();

    #pragma unroll 1
    for (int s = 0; s < 10; ++s) {
        if (s < 9) {
            int k0n = (s+1)*16;
            int d = k0n + lq*4;
            const float* src;
            if (d < 100)      src = we + (size_t)wi*100 + d;
            else if (d < 120) src = te + ti*20 + (d-100);
            else if (d < 140) src = p1e + pi1*20 + (d-120);
            else              src = p2e + pi2*20 + (d-140);
            aR = *(const float4*)src;
            const float* wb = W + (size_t)(n0 + wrow)*160 + k0n + wq*8;
            wR0 = *(const float4*)(wb);
            wR1 = *(const float4*)(wb + 4);
        }
        #pragma unroll
        for (int kk = 0; kk < 16; ++kk) {
            float4 a4  = *(const float4*)&As[kk*GA_S + ty*4];
            float4 w4a = *(const float4*)&Ws[kk*GW_S + tx*8];
            float4 w4b = *(const float4*)&Ws[kk*GW_S + tx*8 + 4];
            float2 w0 = make_float2(w4a.x, w4a.y);
            float2 w1 = make_float2(w4a.z, w4a.w);
            float2 w2 = make_float2(w4b.x, w4b.y);
            float2 w3 = make_float2(w4b.z, w4b.w);
            float2 da;
            da = dup2(a4.x);
            acc[0][0]=ffma2(da,w0,acc[0][0]); acc[0][1]=ffma2(da,w1,acc[0][1]);
            acc[0][2]=ffma2(da,w2,acc[0][2]); acc[0][3]=ffma2(da,w3,acc[0][3]);
            da = dup2(a4.y);
            acc[1][0]=ffma2(da,w0,acc[1][0]); acc[1][1]=ffma2(da,w1,acc[1][1]);
            acc[1][2]=ffma2(da,w2,acc[1][2]); acc[1][3]=ffma2(da,w3,acc[1][3]);
            da = dup2(a4.z);
            acc[2][0]=ffma2(da,w0,acc[2][0]); acc[2][1]=ffma2(da,w1,acc[2][1]);
            acc[2][2]=ffma2(da,w2,acc[2][2]); acc[2][3]=ffma2(da,w3,acc[2][3]);
            da = dup2(a4.w);
            acc[3][0]=ffma2(da,w0,acc[3][0]); acc[3][1]=ffma2(da,w1,acc[3][1]);
            acc[3][2]=ffma2(da,w2,acc[3][2]); acc[3][3]=ffma2(da,w3,acc[3][3]);
        }
        __syncthreads();
        if (s < 9) {
            As[(lq*4+0)*GA_S + lrow] = aR.x;
            As[(lq*4+1)*GA_S + lrow] = aR.y;
            As[(lq*4+2)*GA_S + lrow] = aR.z;
            As[(lq*4+3)*GA_S + lrow] = aR.w;
            Ws[(wq*8+0)*GW_S + wrow] = wR0.x;
            Ws[(wq*8+1)*GW_S + wrow] = wR0.y;
            Ws[(wq*8+2)*GW_S + wrow] = wR0.z;
            Ws[(wq*8+3)*GW_S + wrow] = wR0.w;
            Ws[(wq*8+4)*GW_S + wrow] = wR1.x;
            Ws[(wq*8+5)*GW_S + wrow] = wR1.y;
            Ws[(wq*8+6)*GW_S + wrow] = wR1.z;
            Ws[(wq*8+7)*GW_S + wrow] = wR1.w;
            __syncthreads();
        }
    }

    int nb = n0 + tx*8;
    float4 biA = *(const float4*)&bi[nb];
    float4 biB = *(const float4*)&bi[nb+4];
    float4 bhA = *(const float4*)&bh[nb];
    float4 bhB = *(const float4*)&bh[nb+4];
    float b0v = biA.x+bhA.x, b1v = biA.y+bhA.y, b2v = biA.z+bhA.z, b3v = biA.w+bhA.w;
    float b4v = biB.x+bhB.x, b5v = biB.y+bhB.y, b6v = biB.z+bhB.z, b7v = biB.w+bhB.w;
    #pragma unroll
    for (int i = 0; i < 4; ++i) {
        int m = m0 + ty*4 + i;
        float4 o0 = make_float4(acc[i][0].x + b0v, acc[i][0].y + b1v,
                                acc[i][1].x + b2v, acc[i][1].y + b3v);
        float4 o1 = make_float4(acc[i][2].x + b4v, acc[i][2].y + b5v,
                                acc[i][3].x + b6v, acc[i][3].y + b7v);
        *(float4*)&C[(size_t)m*1024 + nb]     = o0;
        *(float4*)&C[(size_t)m*1024 + nb + 4] = o1;
    }
}

// ---------------- K2: persistent BiLSTM with 16-block flag sync ----------------
#define WT_F4 (4*64*17)
#define HS_F4 (16*69)
#define LSTM_SMEM ((WT_F4 + HS_F4) * 16)

__global__ void __launch_bounds__(256, 2) lstm_kernel(
        const float* __restrict__ whh_f, const float* __restrict__ whh_b) {
    extern __shared__ float4 sm4[];
    float4* w_t = sm4;
    float4* h_s = sm4 + WT_F4;
    int blk = blockIdx.x;
    int dir = blk >> 7;
    int rem = blk & 127;
    int bt = rem >> 4;
    int ut = rem & 15;
    int gid = dir * 8 + bt;
    int b0 = bt * 16;
    int u0 = ut * 16;
    int tid = threadIdx.x;
    int ww = tid >> 5, lane = tid & 31;
    int b_local = (ww >> 1) * 4 + (lane >> 3);
    int u_local = (ww & 1) * 8 + (lane & 7);
    int b = b0 + b_local;
    int u = u0 + u_local;
    const float* whh = dir ? whh_b : whh_f;
    const float* xg  = dir ? g_xgb : g_xgf;
    float* xout      = dir ? g_xb  : g_xf;

    for (int x = tid; x < 4*64*16; x += 256) {
        int uu = x & 15;
        int k4 = (x >> 4) & 63;
        int g  = x >> 10;
        int R  = g*256 + u0 + uu;
        float4 v = *(const float4*)(whh + (size_t)R*256 + k4*4);
        w_t[(g*64 + k4)*17 + uu] = v;
    }
    __syncthreads();

    const float4* hrow = h_s + b_local*69;
    const float4* wp = w_t + u_local;

    int t0 = dir ? (LL-1) : 0;
    const float* xgp0 = xg + ((size_t)(b*LL + t0))*1024 + u;
    float xc0 = xgp0[0], xc1 = xgp0[256], xc2 = xgp0[512], xc3 = xgp0[768];

    float c_reg = 0.f;
    for (int s = 0; s < LL; ++s) {
        int t = dir ? (LL-1-s) : s;
        if (s > 0) {
            if (tid < 16) {
                const int* fp = &g_hflags[gid][tid];
                int v;
                do {
                    asm volatile("ld.acquire.gpu.global.s32 %0, [%1];" : "=r"(v) : "l"(fp));
                } while (v < s);
            }
            __syncthreads();
        }
        const float4* hsrc = (const float4*)(g_hbuf + ((size_t)((s&3)*2 + dir)*BB + b0)*HID);
        for (int x = tid; x < 16*64; x += 256) {
            float4 v = __ldcg(hsrc + x);
            h_s[(x >> 6)*69 + (x & 63)] = v;
        }
        __syncthreads();

        float2 a0 = make_float2(0.f,0.f), a1 = make_float2(0.f,0.f);
        float2 a2 = make_float2(0.f,0.f), a3 = make_float2(0.f,0.f);
        #pragma unroll 8
        for (int k4 = 0; k4 < 64; ++k4) {
            float4 h4 = hrow[k4];
            float2 hA = make_float2(h4.x, h4.y);
            float2 hB = make_float2(h4.z, h4.w);
            float4 w;
            w = wp[(0*64 + k4)*17]; a0 = ffma2(hA, make_float2(w.x,w.y), a0); a0 = ffma2(hB, make_float2(w.z,w.w), a0);
            w = wp[(1*64 + k4)*17]; a1 = ffma2(hA, make_float2(w.x,w.y), a1); a1 = ffma2(hB, make_float2(w.z,w.w), a1);
            w = wp[(2*64 + k4)*17]; a2 = ffma2(hA, make_float2(w.x,w.y), a2); a2 = ffma2(hB, make_float2(w.z,w.w), a2);
            w = wp[(3*64 + k4)*17]; a3 = ffma2(hA, make_float2(w.x,w.y), a3); a3 = ffma2(hB, make_float2(w.z,w.w), a3);
        }
        float gi = xc0 + a0.x + a0.y;
        float gf = xc1 + a1.x + a1.y;
        float gg = xc2 + a2.x + a2.y;
        float go = xc3 + a3.x + a3.y;
        float ig = 1.f / (1.f + expf(-gi));
        float fg = 1.f / (1.f + expf(-gf));
        float gt = tanhf(gg);
        float og = 1.f / (1.f + expf(-go));
        c_reg = fg * c_reg + ig * gt;
        float h = og * tanhf(c_reg);
        g_hbuf[((size_t)(((s+1)&3)*2 + dir)*BB + b)*HID + u] = h;
        xout[((size_t)(b*LL + t))*HID + u] = h;

        if (s + 1 < LL) {
            int tn = dir ? (LL-2-s) : (s+1);
            const float* xgp = xg + ((size_t)(b*LL + tn))*1024 + u;
            xc0 = xgp[0]; xc1 = xgp[256]; xc2 = xgp[512]; xc3 = xgp[768];
            __threadfence();
            __syncthreads();
            if (tid == 0) {
                int* fp = &g_hflags[gid][ut];
                int fv = s + 1;
                asm volatile("st.release.gpu.global.s32 [%0], %1;" :: "l"(fp), "r"(fv));
            }
        }
    }
}

// ---------------- K3: fused post, warp-per-l ----------------
__global__ void __launch_bounds__(256) post_kernel(const int* __restrict__ pos1,
                                                   const int* __restrict__ pos2) {
    int b = blockIdx.x;
    int tid = threadIdx.x;
    int w = tid >> 5, lane = tid & 31;
    __shared__ int e1s, e2s;
    __shared__ float he_s[256];
    __shared__ float lg[100];
    if (tid < 100) {
        if (pos1[b*100 + tid] == 68) e1s = tid;
        if (pos2[b*100 + tid] == 68) e2s = tid;
    }
    g_s[b*304 + tid] = 0.f;
    if (tid < 48) g_s[b*304 + 256 + tid] = 0.f;
    __syncthreads();
    {
        size_t r1 = (size_t)(b*100 + e1s)*256 + tid;
        size_t r2 = (size_t)(b*100 + e2s)*256 + tid;
        he_s[tid] = g_xf[r1] + g_xb[r1] + g_xf[r2] + g_xb[r2];
    }
    __syncthreads();

    for (int l = w; l < 100; l += 8) {
        size_t base = (size_t)(b*100 + l)*256 + lane*8;
        float4 f0 = *(const float4*)(g_xf + base);
        float4 f1 = *(const float4*)(g_xf + base + 4);
        float4 b0v = *(const float4*)(g_xb + base);
        float4 b1v = *(const float4*)(g_xb + base + 4);
        float xv[8];
        xv[0]=f0.x+b0v.x; xv[1]=f0.y+b0v.y; xv[2]=f0.z+b0v.z; xv[3]=f0.w+b0v.w;
        xv[4]=f1.x+b1v.x; xv[5]=f1.y+b1v.y; xv[6]=f1.z+b1v.z; xv[7]=f1.w+b1v.w;
        float sq = 0.f;
        #pragma unroll
        for (int j = 0; j < 8; ++j) sq += xv[j]*xv[j];
        float n2 = sq + __shfl_xor_sync(0xffffffffu, sq, 1);
        float sc = (n2 / (1.f + n2)) * rsqrtf(n2 + 1e-9f);
        float* up = g_u + (size_t)b*25600 + l*256 + lane*8;
        float4 o0 = make_float4(xv[0]*sc, xv[1]*sc, xv[2]*sc, xv[3]*sc);
        float4 o1 = make_float4(xv[4]*sc, xv[5]*sc, xv[6]*sc, xv[7]*sc);
        *(float4*)up = o0; *(float4*)(up+4) = o1;
        float pr = 0.f;
        #pragma unroll
        for (int j = 0; j < 8; ++j) pr += xv[j] * he_s[lane*8 + j];
        #pragma unroll
        for (int o2 = 16; o2; o2 >>= 1) pr += __shfl_xor_sync(0xffffffffu, pr, o2);
        if (lane == 0) lg[l] = pr;
    }
    __syncthreads();
    if (w == 0) {
        float mv = -1e30f;
        #pragma unroll
        for (int r = 0; r < 4; ++r) {
            int l = lane + r*32;
            if (l < 100) mv = fmaxf(mv, lg[l]);
        }
        #pragma unroll
        for (int o2 = 16; o2; o2 >>= 1) mv = fmaxf(mv, __shfl_xor_sync(0xffffffffu, mv, o2));
        float ssum = 0.f;
        #pragma unroll
        for (int r = 0; r < 4; ++r) {
            int l = lane + r*32;
            if (l < 100) ssum += expf(lg[l] - mv);
        }
        #pragma unroll
        for (int o2 = 16; o2; o2 >>= 1) ssum += __shfl_xor_sync(0xffffffffu, ssum, o2);
        #pragma unroll
        for (int r = 0; r < 4; ++r) {
            int l = lane + r*32;
            if (l < 100) g_att[b*100 + l] = expf(lg[l] - mv) / ssum;
        }
    }
}

// ---------------- K4: routing pass — class-aligned od ownership ----------------
__global__ void __launch_bounds__(320) route_kernel(int first, int last,
        const float* __restrict__ broute, const float* __restrict__ Wc) {
    __shared__ float2 Wb[2][16*152];
    __shared__ float  u_s[2][16*17];
    __shared__ float  bbsm[16][20];
    __shared__ float  csm[16][20];

    int ichunk = blockIdx.x >> 3;
    int bch    = blockIdx.x & 7;
    int i0 = ichunk * 50;
    int tid = threadIdx.x;
    int bp = tid & 7;
    int q  = tid >> 3;
    bool act = q < 38;
    int qc = act ? q : 37;
    int o  = qc >> 1;
    int b0g = bch*16;

    float2 vv[2][4];
    #pragma unroll
    for (int j = 0; j < 2; ++j)
        #pragma unroll
        for (int p = 0; p < 4; ++p) vv[j][p] = make_float2(0.f, 0.f);
    if (!first && act) {
        #pragma unroll
        for (int j = 0; j < 2; ++j)
            #pragma unroll
            for (int p = 0; p < 4; ++p)
                vv[j][p] = *(const float2*)&g_v[(b0g + 2*bp + j)*ODIM + 8*qc + 2*p];
    }

    {
        const float4* src = (const float4*)(Wc + (size_t)i0 * 4864);
        float4* dst = (float4*)&Wb[0][0];
        for (int x = tid; x < 1216; x += 320) dst[x] = src[x];
        if (tid < 64) {
            int br = tid >> 2, c4 = (tid & 3) * 4;
            float4 uv = *(const float4*)&g_u[(size_t)(b0g + br)*25600 + i0*16 + c4];
            u_s[0][br*17 + c4 + 0] = uv.x; u_s[0][br*17 + c4 + 1] = uv.y;
            u_s[0][br*17 + c4 + 2] = uv.z; u_s[0][br*17 + c4 + 3] = uv.w;
        }
    }
    float2 sa[2][4];
    #pragma unroll
    for (int j = 0; j < 2; ++j)
        #pragma unroll
        for (int p = 0; p < 4; ++p) sa[j][p] = make_float2(0.f, 0.f);
    __syncthreads();

    for (int ii = 0; ii < 50; ++ii) {
        int i = i0 + ii;
        int cur = ii & 1, nxt = cur ^ 1;
        const float2* Wcur = &Wb[cur][0];
        const float*  Ucur = &u_s[cur][0];

        float4 pf0, pf1, pf2, pf3, pfu;
        if (ii < 49) {
            const float4* src = (const float4*)(Wc + (size_t)(i+1) * 4864);
            pf0 = src[tid];
            pf1 = src[tid + 320];
            pf2 = src[tid + 640];
            if (tid + 960 < 1216) pf3 = src[tid + 960];
            if (tid < 64) {
                int br = tid >> 2, c4 = (tid & 3) * 4;
                pfu = *(const float4*)&g_u[(size_t)(b0g + br)*25600 + (i+1)*16 + c4];
            }
        }

        float2 uh[2][4];
        #pragma unroll
        for (int j = 0; j < 2; ++j)
            #pragma unroll
            for (int p = 0; p < 4; ++p) uh[j][p] = make_float2(0.f, 0.f);
        #pragma unroll
        for (int c = 0; c < 16; ++c) {
            const float4* wrow = (const float4*)(Wcur + c*152 + 4*qc);
            float4 wA = wrow[0];
            float4 wB = wrow[1];
            float2 w0 = make_float2(wA.x, wA.y);
            float2 w1 = make_float2(wA.z, wA.w);
            float2 w2 = make_float2(wB.x, wB.y);
            float2 w3 = make_float2(wB.z, wB.w);
            float ua = Ucur[(2*bp + 0)*17 + c];
            float ub = Ucur[(2*bp + 1)*17 + c];
            float2 ua2 = make_float2(ua, ua);
            float2 ub2 = make_float2(ub, ub);
            uh[0][0] = ffma2(ua2, w0, uh[0][0]); uh[0][1] = ffma2(ua2, w1, uh[0][1]);
            uh[0][2] = ffma2(ua2, w2, uh[0][2]); uh[0][3] = ffma2(ua2, w3, uh[0][3]);
            uh[1][0] = ffma2(ub2, w0, uh[1][0]); uh[1][1] = ffma2(ub2, w1, uh[1][1]);
            uh[1][2] = ffma2(ub2, w2, uh[1][2]); uh[1][3] = ffma2(ub2, w3, uh[1][3]);
        }

        if (!first) {
            #pragma unroll
            for (int j = 0; j < 2; ++j) {
                float p = 0.f;
                #pragma unroll
                for (int pp = 0; pp < 4; ++pp)
                    p += uh[j][pp].x*vv[j][pp].x + uh[j][pp].y*vv[j][pp].y;
                p += __shfl_xor_sync(0xffffffffu, p, 8);
                if (act && (q & 1) == 0) bbsm[2*bp + j][o] = p;
            }
        }
        __syncthreads();

        int warp = tid >> 5, lane = tid & 31;
        if (warp < 8) {
            #pragma unroll
            for (int rep = 0; rep < 2; ++rep) {
                int bsel = warp + rep*8;
                int bglob = b0g + bsel;
                float bbv = 0.f;
                if (lane < 19) {
                    if (first) bbv = broute[i*NCLS + lane];
                    else       bbv = g_bb[((size_t)bglob*NCAP + i)*NCLS + lane] + bbsm[bsel][lane];
                    if (!last) g_bb[((size_t)bglob*NCAP + i)*NCLS + lane] = bbv;
                }
                float val = (lane < 19) ? bbv : -1e30f;
                float m = val;
                #pragma unroll
                for (int o2 = 16; o2; o2 >>= 1) m = fmaxf(m, __shfl_xor_sync(0xffffffffu, m, o2));
                float e = (lane < 19) ? expf(val - m) : 0.f;
                float ssum = e;
                #pragma unroll
                for (int o2 = 16; o2; o2 >>= 1) ssum += __shfl_xor_sync(0xffffffffu, ssum, o2);
                float attv = g_att[bglob*LL + (i >> 4)];
                if (lane < 19) csm[bsel][lane] = (e / ssum) * attv;
            }
        }
        if (ii < 49) {
            float4* Wn = (float4*)&Wb[nxt][0];
            Wn[tid]       = pf0;
            Wn[tid + 320] = pf1;
            Wn[tid + 640] = pf2;
            if (tid + 960 < 1216) Wn[tid + 960] = pf3;
            if (tid < 64) {
                int br = tid >> 2, c4 = (tid & 3) * 4;
                u_s[nxt][br*17 + c4 + 0] = pfu.x; u_s[nxt][br*17 + c4 + 1] = pfu.y;
                u_s[nxt][br*17 + c4 + 2] = pfu.z; u_s[nxt][br*17 + c4 + 3] = pfu.w;
            }
        }
        __syncthreads();

        #pragma unroll
        for (int j = 0; j < 2; ++j) {
            float cc = csm[2*bp + j][o];
            float2 cc2 = make_float2(cc, cc);
            #pragma unroll
            for (int p = 0; p < 4; ++p)
                sa[j][p] = ffma2(cc2, uh[j][p], sa[j][p]);
        }
    }

    if (act) {
        #pragma unroll
        for (int j = 0; j < 2; ++j) {
            int brow = (b0g + 2*bp + j) * ODIM;
            #pragma unroll
            for (int p = 0; p < 4; ++p) {
                int od = 8*qc + 2*p;
                atomicAdd(&g_s[brow + od],     sa[j][p].x);
                atomicAdd(&g_s[brow + od + 1], sa[j][p].y);
            }
        }
    }
}

// ---------------- K5: v = squash(s), zero g_s, final lengths ----------------
__global__ void squash_v_kernel(float* __restrict__ out, int last) {
    int idx = blockIdx.x * blockDim.x + threadIdx.x;
    if (idx >= BB*NCLS) return;
    float* sp = g_s + (size_t)idx * 16;
    float4 a0 = *(const float4*)(sp + 0);
    float4 a1 = *(const float4*)(sp + 4);
    float4 a2 = *(const float4*)(sp + 8);
    float4 a3 = *(const float4*)(sp + 12);
    float n2 = a0.x*a0.x + a0.y*a0.y + a0.z*a0.z + a0.w*a0.w
             + a1.x*a1.x + a1.y*a1.y + a1.z*a1.z + a1.w*a1.w
             + a2.x*a2.x + a2.y*a2.y + a2.z*a2.z + a2.w*a2.w
             + a3.x*a3.x + a3.y*a3.y + a3.z*a3.z + a3.w*a3.w;
    float sc = (n2 / (1.f + n2)) * rsqrtf(n2 + 1e-9f);
    float* vp = g_v + (size_t)idx * 16;
    a0.x*=sc; a0.y*=sc; a0.z*=sc; a0.w*=sc;
    a1.x*=sc; a1.y*=sc; a1.z*=sc; a1.w*=sc;
    a2.x*=sc; a2.y*=sc; a2.z*=sc; a2.w*=sc;
    a3.x*=sc; a3.y*=sc; a3.z*=sc; a3.w*=sc;
    *(float4*)(vp + 0)  = a0; *(float4*)(vp + 4)  = a1;
    *(float4*)(vp + 8)  = a2; *(float4*)(vp + 12) = a3;
    float4 z = make_float4(0.f, 0.f, 0.f, 0.f);
    *(float4*)(sp + 0) = z; *(float4*)(sp + 4)  = z;
    *(float4*)(sp + 8) = z; *(float4*)(sp + 12) = z;
    if (last) out[idx] = sqrtf(n2 * sc * sc + 1e-9f);
}

// ---------------- launch ----------------
extern "C" void kernel_launch(void* const* d_in, const int* in_sizes, int n_in,
                              void* d_out, int out_size) {
    const int*   word   = (const int*)d_in[0];
    const int*   tag    = (const int*)d_in[1];
    const int*   pos1   = (const int*)d_in[2];
    const int*   pos2   = (const int*)d_in[3];
    const float* we     = (const float*)d_in[4];
    const float* te     = (const float*)d_in[5];
    const float* p1e    = (const float*)d_in[6];
    const float* p2e    = (const float*)d_in[7];
    const float* wihf   = (const float*)d_in[8];
    const float* whhf   = (const float*)d_in[9];
    const float* bihf   = (const float*)d_in[10];
    const float* bhhf   = (const float*)d_in[11];
    const float* wihb   = (const float*)d_in[12];
    const float* whhb   = (const float*)d_in[13];
    const float* bihb   = (const float*)d_in[14];
    const float* bhhb   = (const float*)d_in[15];
    const float* wcaps  = (const float*)d_in[16];
    const float* broute = (const float*)d_in[17];
    float* out = (float*)d_out;

    cudaFuncSetAttribute(lstm_kernel, cudaFuncAttributeMaxDynamicSharedMemorySize, LSTM_SMEM);

    dim3 gg(8, 200, 2);
    gemm_xg_kernel<<<gg, 256>>>(word, tag, pos1, pos2, we, te, p1e, p2e,
                                wihf, wihb, bihf, bhhf, bihb, bhhb);     // launch 1 (also resets lstm state)

    lstm_kernel<<<256, 256, LSTM_SMEM>>>(whhf, whhb);                    // launch 2

    post_kernel<<<BB, 256>>>(pos1, pos2);                                // launch 3

    for (int it = 0; it < 3; ++it) {
        route_kernel<<<256, 320>>>(it == 0 ? 1 : 0, it == 2 ? 1 : 0, broute, wcaps); // launch 4 = ncu slot (pass 1)
        squash_v_kernel<<<(BB*NCLS + 127)/128, 128>>>(out, it == 2 ? 1 : 0);
    }
    (void)in_sizes; (void)n_in; (void)out_size;
}